// round 16
// baseline (speedup 1.0000x reference)
#include <cuda_runtime.h>

#define EPSV 1e-5f
#define RSQRT8 0.35355339059327373f

// scratch (allocation-free rule: device globals)
__device__ float g_q[4*512*64];
__device__ float g_k[4*512*64];
__device__ float g_v[4*512*64];
__device__ float g_y[4*512*64];

typedef unsigned long long ull;

__device__ __forceinline__ ull splat2(float x){
    ull r; unsigned u = __float_as_uint(x);
    asm("mov.b64 %0, {%1,%1};" : "=l"(r) : "r"(u));
    return r;
}
__device__ __forceinline__ void fma2a(ull& d, ull a, ull b){
    asm("fma.rn.f32x2 %0, %1, %2, %0;" : "+l"(d) : "l"(a), "l"(b));
}
__device__ __forceinline__ ull mul2(ull a, ull b){
    ull d; asm("mul.rn.f32x2 %0, %1, %2;" : "=l"(d) : "l"(a), "l"(b));
    return d;
}
__device__ __forceinline__ void add2a(ull& d, ull a){
    asm("add.rn.f32x2 %0, %0, %1;" : "+l"(d) : "l"(a));
}
__device__ __forceinline__ float2 unpack2(ull v){
    unsigned lo, hi;
    asm("mov.b64 {%0,%1}, %2;" : "=r"(lo), "=r"(hi) : "l"(v));
    return make_float2(__uint_as_float(lo), __uint_as_float(hi));
}
__device__ __forceinline__ float hsum2(ull v){
    float2 u = unpack2(v); return u.x + u.y;
}
__device__ __forceinline__ void cpa16(const void* sd, const void* g){
    unsigned s = (unsigned)__cvta_generic_to_shared(sd);
    asm volatile("cp.async.cg.shared.global [%0], [%1], 16;" :: "r"(s), "l"(g));
}
__device__ __forceinline__ unsigned tf32r(float x){
    unsigned r; asm("cvt.rna.tf32.f32 %0, %1;" : "=r"(r) : "f"(x)); return r;
}
__device__ __forceinline__ void mma8(float* d, unsigned a0, unsigned a1, unsigned a2, unsigned a3,
                                     unsigned b0, unsigned b1){
    asm("mma.sync.aligned.m16n8k8.row.col.f32.tf32.tf32.f32 "
        "{%0,%1,%2,%3},{%4,%5,%6,%7},{%8,%9},{%0,%1,%2,%3};"
        : "+f"(d[0]), "+f"(d[1]), "+f"(d[2]), "+f"(d[3])
        : "r"(a0), "r"(a1), "r"(a2), "r"(a3), "r"(b0), "r"(b1));
}

// ===================== Kernel 1: LN1 + QKV projection (4 rows/block) =====================
__global__ void __launch_bounds__(256)
qkv_kernel(const float* __restrict__ h, const float* __restrict__ Wh,
           const float* __restrict__ g1, const float* __restrict__ b1)
{
    __shared__ float hn[4][64];
    __shared__ float part[4][4];
    int t = threadIdx.x;
    int g = t >> 6, tl = t & 63;
    int row = blockIdx.x*4 + g;
    float x = h[row*64 + tl];
    float s = x, q = x*x;
    #pragma unroll
    for (int o = 16; o >= 1; o >>= 1){
        s += __shfl_xor_sync(0xffffffffu, s, o);
        q += __shfl_xor_sync(0xffffffffu, q, o);
    }
    if ((tl & 31) == 0){ part[g][tl>>5] = s; part[g][2 + (tl>>5)] = q; }
    __syncthreads();
    float mean = (part[g][0] + part[g][1]) * (1.f/64.f);
    float var  = (part[g][2] + part[g][3]) * (1.f/64.f) - mean*mean;
    float hv = (x - mean) * rsqrtf(var + EPSV) * g1[tl] + b1[tl];
    hn[g][tl] = hv;
    __syncthreads();
    float aq = 0.f, ak = 0.f, av = 0.f;
    #pragma unroll 8
    for (int i = 0; i < 64; i++){
        float z = hn[g][i];
        aq = fmaf(z, Wh[i*192 + tl],       aq);
        ak = fmaf(z, Wh[i*192 + 64 + tl],  ak);
        av = fmaf(z, Wh[i*192 + 128 + tl], av);
    }
    g_q[row*64 + tl] = aq;
    g_k[row*64 + tl] = ak;
    g_v[row*64 + tl] = av;
}

// ===================== Kernel 2: one-warp blocks, all 148 SMs (R15 inner loop) =====================
// 2048 blocks x 32 threads; block = ONE warp = ONE q-row. ~14 warps/SM, single balanced wave.
// 16 k-rows/tile, 32 tiles, warp-private double buffer, prefetch distance 1, __syncwarp only.
// Phase1: ew[16x16] = E[16x64]@We[64x16] via mma m16n8k8 (B rna in regs, A raw f32 bits).
// Phase2: coalesced k/v (lane*16 within 512B 2-row groups); half-head dot + shfl_xor(1).
// y -> g_y. smem: e_w [2][1088] @0 | ew_w [16][20] @2176 -> 2496 fl = 9984 B.
__global__ void __launch_bounds__(32, 14)
attn_kernel(const float* __restrict__ e, const float* __restrict__ We)
{
    extern __shared__ float smem[];
    float* e_w  = smem;          // [2][1088]
    float* ew_w = smem + 2176;   // [16][20]

    const int lane = threadIdx.x;
    const int hh     = (lane >> 1) & 7;  // head
    const int half   = lane & 1;         // 16B half of the head's 32B
    const int rowpar = lane >> 4;        // row parity within 2-row group
    const int qrow = blockIdx.x;         // global row id (b*512 + n)
    const int b    = qrow >> 9;

    // ---- per-lane copy addressing (e tile: 16 rows x 64 floats) ----
    const int crow = lane >> 4;
    const int cch  = lane & 15;
    const char* pe = (const char*)(e + (size_t)qrow*32768) + crow*256 + cch*16;
    char* ed0 = (char*)e_w + crow*272 + cch*16;

    // ---- issue tile 0 ----
    #pragma unroll
    for (int i = 0; i < 8; i++) cpa16(ed0 + i*544, pe + i*512);
    asm volatile("cp.async.commit_group;");
    pe += 4096;

    // ---- persistent B fragments (rna tf32) + q half-head regs ----
    unsigned b0f[16], b1f[16];
    {
        const int kq = lane & 3, nq = lane >> 2;
        #pragma unroll
        for (int s = 0; s < 8; s++){
            #pragma unroll
            for (int n = 0; n < 2; n++){
                b0f[s*2+n] = tf32r(We[(s*8 + kq)*16 + n*8 + nq]);
                b1f[s*2+n] = tf32r(We[(s*8 + kq + 4)*16 + n*8 + nq]);
            }
        }
    }
    ull qh0, qh1;
    {
        const ull* qp = (const ull*)(g_q + (size_t)qrow*64 + hh*8 + half*4);
        qh0 = qp[0]; qh1 = qp[1];
    }
    const char* pk = (const char*)(g_k + (size_t)(b*512)*64) + lane*16;
    const char* pv = (const char*)(g_v + (size_t)(b*512)*64) + lane*16;

    float l = 0.f;
    ull acc0 = 0ull, acc1 = 0ull;       // half-head output accumulator (4 floats)

    const int r4 = lane >> 2, cq = lane & 3;
    const int ew_rd = 2*hh;

    for (int tile = 0; tile < 32; tile++){
        const int buf = tile & 1;
        if (tile < 31){
            char* ed = (char*)(e_w + (buf^1)*1088) + crow*272 + cch*16;
            #pragma unroll
            for (int i = 0; i < 8; i++) cpa16(ed + i*544, pe + i*512);
            asm volatile("cp.async.commit_group;");
            pe += 4096;
            asm volatile("cp.async.wait_group 1;");
        } else {
            asm volatile("cp.async.wait_group 0;");
        }
        __syncwarp();

        // ---- Phase 1: ew = E[16x64] @ We[64x16] ----
        {
            const float* eA = e_w + buf*1088 + r4*68 + cq;
            float d0[4] = {0.f,0.f,0.f,0.f};
            float d1[4] = {0.f,0.f,0.f,0.f};
            #pragma unroll
            for (int s = 0; s < 8; s++){
                unsigned a0 = __float_as_uint(eA[s*8]);
                unsigned a2 = __float_as_uint(eA[s*8 + 4]);
                unsigned a1 = __float_as_uint(eA[544 + s*8]);
                unsigned a3 = __float_as_uint(eA[544 + s*8 + 4]);
                mma8(d0, a0, a1, a2, a3, b0f[s*2],   b1f[s*2]);
                mma8(d1, a0, a1, a2, a3, b0f[s*2+1], b1f[s*2+1]);
            }
            float* ewp = ew_w + r4*20 + 4*cq;
            *(float4*)ewp         = make_float4(d0[0], d1[0], d0[1], d1[1]);  // {e1,e2} cols 2cq, 2cq+1
            *(float4*)(ewp + 160) = make_float4(d0[2], d1[2], d0[3], d1[3]);  // rows +8
        }
        __syncwarp();

        // ---- Phase 2: coalesced k/v; lane handles (row 2i+rowpar, head hh, half) ----
        #pragma unroll
        for (int i = 0; i < 8; i++){
            ulonglong2 kc = *(const ulonglong2*)(pk + i*512);
            ulonglong2 vc = *(const ulonglong2*)(pv + i*512);
            float2 ez = *(const float2*)(ew_w + (2*i + rowpar)*20 + ew_rd);
            ull s2 = mul2(qh0, kc.x);
            fma2a(s2, qh1, kc.y);
            float sh = hsum2(s2);
            float sfull = sh + __shfl_xor_sync(0xffffffffu, sh, 1);
            float p = __expf(fmaf(sfull, RSQRT8, ez.x));
            l += p;
            ull gv = splat2(p * ez.y);
            fma2a(acc0, gv, vc.x);
            fma2a(acc1, gv, vc.y);
        }
        pk += 4096; pv += 4096;
        __syncwarp();
    }

    // ---- reduce over rowpar (xor 16) ----
    l += __shfl_xor_sync(0xffffffffu, l, 16);
    add2a(acc0, __shfl_xor_sync(0xffffffffu, acc0, 16));
    add2a(acc1, __shfl_xor_sync(0xffffffffu, acc1, 16));

    if (rowpar == 0){
        float inv = __fdividef(1.f, l);
        float2 u0 = unpack2(acc0);
        float2 u1 = unpack2(acc1);
        float4 yv = make_float4(u0.x*inv, u0.y*inv, u1.x*inv, u1.y*inv);
        *(float4*)(g_y + (size_t)qrow*64 + hh*8 + half*4) = yv;
    }
}

// ===================== Kernel 3: epilogue — LN2 + MLP + residual (4 rows/block) =====================
__global__ void __launch_bounds__(256)
epi_kernel(const float* __restrict__ hin, const float* __restrict__ w1,
           const float* __restrict__ w2, const float* __restrict__ g2,
           const float* __restrict__ b2, float* __restrict__ out)
{
    __shared__ float y_s[256];
    __shared__ float z_s[256];
    __shared__ float hid_s[1024];

    const int t  = threadIdx.x;
    const int w  = t >> 5;
    const int lane = t & 31;
    const int q0 = blockIdx.x * 4;      // global row base

    y_s[t] = g_y[(size_t)q0*64 + t];
    __syncthreads();

    // ---- LN2 over (y + h_in): warps 0..3 -> rows 0..3 ----
    if (w < 4){
        const float* hrow = hin + (size_t)(q0 + w) * 64;
        float x0 = y_s[w*64 + lane]      + hrow[lane];
        float x1 = y_s[w*64 + lane + 32] + hrow[lane + 32];
        float s = x0 + x1, sq = x0*x0 + x1*x1;
        #pragma unroll
        for (int o = 16; o >= 1; o >>= 1){
            s  += __shfl_xor_sync(0xffffffffu, s, o);
            sq += __shfl_xor_sync(0xffffffffu, sq, o);
        }
        float mean = s * (1.f/64.f);
        float var  = sq * (1.f/64.f) - mean*mean;
        float rs = rsqrtf(var + EPSV);
        z_s[w*64 + lane]      = (x0 - mean) * rs * g2[lane]      + b2[lane];
        z_s[w*64 + lane + 32] = (x1 - mean) * rs * g2[lane + 32] + b2[lane + 32];
    }
    __syncthreads();

    // ---- hidden = relu(z @ w1)  [4 x 256]: one column per thread ----
    {
        int col = t;
        float a0 = 0.f, a1 = 0.f, a2 = 0.f, a3 = 0.f;
        #pragma unroll 8
        for (int i = 0; i < 64; i++){
            float wvv = w1[i*256 + col];
            a0 = fmaf(z_s[i],       wvv, a0);
            a1 = fmaf(z_s[64 + i],  wvv, a1);
            a2 = fmaf(z_s[128 + i], wvv, a2);
            a3 = fmaf(z_s[192 + i], wvv, a3);
        }
        hid_s[col]       = fmaxf(a0, 0.f);
        hid_s[256 + col] = fmaxf(a1, 0.f);
        hid_s[512 + col] = fmaxf(a2, 0.f);
        hid_s[768 + col] = fmaxf(a3, 0.f);
    }
    __syncthreads();

    // ---- out = hidden @ w2 + y : one output element per thread ----
    {
        int d = t & 63, r = t >> 6;
        float a = 0.f;
        #pragma unroll 8
        for (int j = 0; j < 256; j++)
            a = fmaf(hid_s[r*256 + j], w2[j*64 + d], a);
        out[(size_t)(q0 + r)*64 + d] = a + y_s[r*64 + d];
    }
}

extern "C" void kernel_launch(void* const* d_in, const int* in_sizes, int n_in,
                              void* d_out, int out_size)
{
    const float* h  = (const float*)d_in[0];
    const float* e  = (const float*)d_in[1];
    const float* Wh = (const float*)d_in[2];
    const float* We = (const float*)d_in[3];
    const float* w1 = (const float*)d_in[4];
    const float* w2 = (const float*)d_in[5];
    const float* g1 = (const float*)d_in[6];
    const float* b1 = (const float*)d_in[7];
    const float* g2 = (const float*)d_in[8];
    const float* b2 = (const float*)d_in[9];
    float* out = (float*)d_out;

    cudaFuncSetAttribute(attn_kernel, cudaFuncAttributeMaxDynamicSharedMemorySize, 9984);

    qkv_kernel<<<512, 256>>>(h, Wh, g1, b1);
    attn_kernel<<<2048, 32, 9984>>>(e, We);
    epi_kernel<<<512, 256>>>(h, w1, w2, g2, b2, out);
}